// round 16
// baseline (speedup 1.0000x reference)
#include <cuda_runtime.h>
#include <cuda_bf16.h>
#include <cstdint>
#include <cstddef>

#define NN 65536
#define EE 262144
#define GG 2048
#define DIN 9
#define HH 300
#define H2 600
#define FF 32
#define LL 5
#define KP1 320
#define KP2 608
#define KPP 1536
#define DGC 1523

// ---------------- scratch (device globals; no allocation allowed) ----------
static __device__ __align__(16) float g_h[(size_t)NN * HH];
static __device__ __align__(16) float g_hv[(size_t)NN * HH];
static __device__ __align__(16) float g_z2[(size_t)NN * HH];
static __device__ __align__(16) float g_vn[(size_t)GG * HH];
static __device__ __align__(16) float g_stats[2 * HH];
static __device__ int g_deg[NN];
static __device__ int g_off[NN + 1];
static __device__ int g_cur[NN];
static __device__ int g_csr[EE];
static __device__ int g_gcnt[GG];
static __device__ int g_gstart[GG];

// split bf16 activation buffers (padded K strides)
static __device__ __align__(16) __nv_bfloat16 g_zinh[(size_t)NN * KP1];
static __device__ __align__(16) __nv_bfloat16 g_zinl[(size_t)NN * KP1];
static __device__ __align__(16) __nv_bfloat16 g_t1h[(size_t)NN * KP2];
static __device__ __align__(16) __nv_bfloat16 g_t1l[(size_t)NN * KP2];
static __device__ __align__(16) __nv_bfloat16 g_vth[(size_t)GG * KP1];
static __device__ __align__(16) __nv_bfloat16 g_vtl[(size_t)GG * KP1];
static __device__ __align__(16) __nv_bfloat16 g_vhh[(size_t)GG * KP2];
static __device__ __align__(16) __nv_bfloat16 g_vhl[(size_t)GG * KP2];
static __device__ __align__(16) __nv_bfloat16 g_hreph[(size_t)GG * KPP];
static __device__ __align__(16) __nv_bfloat16 g_hrepl[(size_t)GG * KPP];
// split transposed weights [L][N][Kp]
static __device__ __align__(16) __nv_bfloat16 g_gW1h[(size_t)LL * H2 * KP1];
static __device__ __align__(16) __nv_bfloat16 g_gW1l[(size_t)LL * H2 * KP1];
static __device__ __align__(16) __nv_bfloat16 g_gW2h[(size_t)LL * HH * KP2];
static __device__ __align__(16) __nv_bfloat16 g_gW2l[(size_t)LL * HH * KP2];
static __device__ __align__(16) __nv_bfloat16 g_vW1h[(size_t)(LL - 1) * H2 * KP1];
static __device__ __align__(16) __nv_bfloat16 g_vW1l[(size_t)(LL - 1) * H2 * KP1];
static __device__ __align__(16) __nv_bfloat16 g_vW2h[(size_t)(LL - 1) * HH * KP2];
static __device__ __align__(16) __nv_bfloat16 g_vW2l[(size_t)(LL - 1) * HH * KP2];
static __device__ __align__(16) __nv_bfloat16 g_Wph[(size_t)H2 * KPP];
static __device__ __align__(16) __nv_bfloat16 g_Wpl[(size_t)H2 * KPP];

#define GSTRIDE(i, n) for (int i = blockIdx.x * blockDim.x + threadIdx.x; \
                           i < (int)(n); i += gridDim.x * blockDim.x)

__device__ __forceinline__ void split_bf16(float v, __nv_bfloat16& hi, __nv_bfloat16& lo) {
    hi = __float2bfloat16_rn(v);
    lo = __float2bfloat16_rn(v - __bfloat162float(hi));
}
__device__ __forceinline__ uint32_t pack2(__nv_bfloat16 a, __nv_bfloat16 b) {
    __nv_bfloat162 t; t.x = a; t.y = b;
    return *(uint32_t*)&t;
}
__device__ __forceinline__ void split_store4(float4 v, __nv_bfloat16* ph, __nv_bfloat16* pl) {
    __nv_bfloat16 h0, l0, h1, l1, h2, l2, h3, l3;
    split_bf16(v.x, h0, l0);
    split_bf16(v.y, h1, l1);
    split_bf16(v.z, h2, l2);
    split_bf16(v.w, h3, l3);
    *(uint2*)ph = make_uint2(pack2(h0, h1), pack2(h2, h3));
    *(uint2*)pl = make_uint2(pack2(l0, l1), pack2(l2, l3));
}
__device__ __forceinline__ uint32_t smem_u32(const void* p) {
    uint32_t a;
    asm("{ .reg .u64 t; cvta.to.shared.u64 t, %1; cvt.u32.u64 %0, t; }" : "=r"(a) : "l"(p));
    return a;
}

// ------------------------- small kernels -----------------------------------
// embed: h = x @ W_emb + b; hv(layer 0) = h + vn0[j]
__global__ void k_embed(const float* __restrict__ x, const float* __restrict__ W,
                        const float* __restrict__ b, const float* __restrict__ vn0) {
    int j = threadIdx.x;
    if (j >= HH) return;
    float bj = b[j];
    float v0 = vn0[j];
    #pragma unroll
    for (int r = 0; r < 4; r++) {
        int node = blockIdx.x * 4 + r;
        const float* xr = x + (size_t)node * DIN;
        float acc = bj;
        #pragma unroll
        for (int k = 0; k < DIN; k++) acc += xr[k] * W[k * HH + j];
        g_h[(size_t)node * HH + j] = acc;
        g_hv[(size_t)node * HH + j] = acc + v0;
    }
}

// fused setup: deg/gcnt zero, out init, pad zero, coalesced vn init
__global__ void k_setup(const float* __restrict__ vn0, const float* __restrict__ bp2,
                        float* __restrict__ out) {
    GSTRIDE(i, NN + GG + GG * HH) {
        if (i < NN) {
            g_deg[i] = 0;
            #pragma unroll
            for (int q = 0; q < 5; q++) {
                *(uint2*)(g_zinh + (size_t)i * KP1 + HH + q * 4) = make_uint2(0, 0);
                *(uint2*)(g_zinl + (size_t)i * KP1 + HH + q * 4) = make_uint2(0, 0);
            }
            *(uint4*)(g_t1h + (size_t)i * KP2 + H2) = make_uint4(0, 0, 0, 0);
            *(uint4*)(g_t1l + (size_t)i * KP2 + H2) = make_uint4(0, 0, 0, 0);
        } else if (i < NN + GG) {
            int r = i - NN;
            g_gcnt[r] = 0;
            out[r] = bp2[0];
            #pragma unroll
            for (int q = 0; q < 5; q++) {
                *(uint2*)(g_vth + (size_t)r * KP1 + HH + q * 4) = make_uint2(0, 0);
                *(uint2*)(g_vtl + (size_t)r * KP1 + HH + q * 4) = make_uint2(0, 0);
            }
            *(uint4*)(g_vhh + (size_t)r * KP2 + H2) = make_uint4(0, 0, 0, 0);
            *(uint4*)(g_vhl + (size_t)r * KP2 + H2) = make_uint4(0, 0, 0, 0);
        } else {
            int idx = i - NN - GG;
            g_vn[idx] = vn0[idx % HH];
        }
    }
}

// fused: blocks [0, vtblocks): vt gather (longest first);
//        blocks [vtblocks, +NN/8): zin gather (+stats zero on first zin block).
// zin[n] = (1+eps)*hv[n] + sum_nb hv[s];  vt[g] = vn[g] + sum_{i in g} hv[i]
__global__ void __launch_bounds__(256, 6) k_gather(const float* __restrict__ eps, int l,
                                                   int vtblocks) {
    int w = threadIdx.x >> 5, lane = threadIdx.x & 31;
    const float4* hv4 = (const float4*)g_hv;
    if ((int)blockIdx.x < vtblocks) {
        int g = ((int)blockIdx.x << 3) + w;
        int s0 = g_gstart[g], c = g_gcnt[g];
        const float4* vn4 = (const float4*)g_vn;
        float4 acc[3];
        #pragma unroll
        for (int q = 0; q < 3; q++) {
            int idx = lane + (q << 5);
            if (idx < 75) acc[q] = vn4[(size_t)g * 75 + idx];
        }
        for (int i = 0; i < c; i++) {
            size_t row = (size_t)(s0 + i) * 75;
            #pragma unroll
            for (int q = 0; q < 3; q++) {
                int idx = lane + (q << 5);
                if (idx < 75) {
                    float4 a = hv4[row + idx];
                    acc[q].x += a.x; acc[q].y += a.y; acc[q].z += a.z; acc[q].w += a.w;
                }
            }
        }
        #pragma unroll
        for (int q = 0; q < 3; q++) {
            int idx = lane + (q << 5);
            if (idx < 75)
                split_store4(acc[q], g_vth + (size_t)g * KP1 + idx * 4,
                             g_vtl + (size_t)g * KP1 + idx * 4);
        }
    } else {
        int zb = (int)blockIdx.x - vtblocks;
        if (zb == 0) {
            for (int i = threadIdx.x; i < 2 * HH; i += 256) g_stats[i] = 0.f;
        }
        int n = (zb << 3) + w;
        float e1 = 1.f + eps[l];
        float4 acc[3];
        #pragma unroll
        for (int q = 0; q < 3; q++) {
            int idx = lane + (q << 5);
            if (idx < 75) {
                float4 a = hv4[(size_t)n * 75 + idx];
                acc[q] = make_float4(e1 * a.x, e1 * a.y, e1 * a.z, e1 * a.w);
            }
        }
        int e0 = g_off[n], e1i = g_off[n + 1];
        for (int e = e0; e < e1i; e++) {
            int s = g_csr[e];
            size_t row = (size_t)s * 75;
            #pragma unroll
            for (int q = 0; q < 3; q++) {
                int idx = lane + (q << 5);
                if (idx < 75) {
                    float4 a = hv4[row + idx];
                    acc[q].x += a.x; acc[q].y += a.y; acc[q].z += a.z; acc[q].w += a.w;
                }
            }
        }
        #pragma unroll
        for (int q = 0; q < 3; q++) {
            int idx = lane + (q << 5);
            if (idx < 75)
                split_store4(acc[q], g_zinh + (size_t)n * KP1 + idx * 4,
                             g_zinl + (size_t)n * KP1 + idx * 4);
        }
    }
}

// fused pool + assemble
__global__ void __launch_bounds__(256, 6) k_poolassemble(const float* __restrict__ morgan,
                                                         const float* __restrict__ maccs) {
    int w = threadIdx.x >> 5, lane = threadIdx.x & 31;
    int g = (blockIdx.x << 3) + w;
    int s0 = g_gstart[g], c = g_gcnt[g];
    const float4* h4 = (const float4*)g_h;
    float4 acc[3];
    #pragma unroll
    for (int q = 0; q < 3; q++) acc[q] = make_float4(0.f, 0.f, 0.f, 0.f);
    for (int i = 0; i < c; i++) {
        size_t row = (size_t)(s0 + i) * 75;
        #pragma unroll
        for (int q = 0; q < 3; q++) {
            int idx = lane + (q << 5);
            if (idx < 75) {
                float4 a = h4[row + idx];
                acc[q].x += a.x; acc[q].y += a.y; acc[q].z += a.z; acc[q].w += a.w;
            }
        }
    }
    float denom = fmaxf((float)c, 1.f);
    __nv_bfloat16* rh = g_hreph + (size_t)g * KPP;
    __nv_bfloat16* rl = g_hrepl + (size_t)g * KPP;
    #pragma unroll
    for (int q = 0; q < 3; q++) {
        int idx = lane + (q << 5);
        if (idx < 75) {
            float4 v = make_float4(acc[q].x / denom, acc[q].y / denom,
                                   acc[q].z / denom, acc[q].w / denom);
            split_store4(v, rh + idx * 4, rl + idx * 4);
        }
    }
    {
        int f = lane;
        int cf = (f < c) ? ((c - 1 - f) / FF + 1) : 0;
        float v = (float)cf / denom;
        __nv_bfloat16 hi, lo;
        split_bf16(v, hi, lo);
        rh[HH + f] = hi;
        rl[HH + f] = lo;
    }
    const float* mg = morgan + (size_t)g * 1024;
    for (int j = lane; j < 1024; j += 32) {
        __nv_bfloat16 hi, lo;
        split_bf16(mg[j], hi, lo);
        rh[HH + FF + j] = hi;
        rl[HH + FF + j] = lo;
    }
    const float* mc = maccs + (size_t)g * 167;
    for (int j = lane; j < 167; j += 32) {
        __nv_bfloat16 hi, lo;
        split_bf16(mc[j], hi, lo);
        rh[HH + FF + 1024 + j] = hi;
        rl[HH + FF + 1024 + j] = lo;
    }
    if (lane < KPP - DGC) {
        __nv_bfloat16 z = __float2bfloat16_rn(0.f);
        rh[DGC + lane] = z;
        rl[DGC + lane] = z;
    }
}

// ---------------------- CSR / segment build --------------------------------
__global__ void k_hist(const int* __restrict__ dst, const int* __restrict__ batch) {
    GSTRIDE(e, EE) atomicAdd(&g_deg[dst[e]], 1);
    GSTRIDE(i, NN) atomicAdd(&g_gcnt[batch[i]], 1);
}
__global__ void k_scatter(const int* __restrict__ src, const int* __restrict__ dst) {
    GSTRIDE(e, EE) {
        int pos = atomicAdd(&g_cur[dst[e]], 1);
        g_csr[pos] = src[e];
    }
}
__global__ void __launch_bounds__(1024) k_scan_both() {
    __shared__ int sh[1024];
    int t = threadIdx.x, w = t >> 5, lane = t & 31;
    if (blockIdx.x == 0) {
        int base = w * 2048;
        int s = 0;
        for (int k = 0; k < 64; k++) s += g_deg[base + k * 32 + lane];
        #pragma unroll
        for (int o = 16; o; o >>= 1) s += __shfl_xor_sync(0xFFFFFFFFu, s, o);
        if (!lane) sh[w] = s;
        __syncthreads();
        if (w == 0) {
            int v = sh[lane];
            int ex = v;
            #pragma unroll
            for (int o = 1; o < 32; o <<= 1) {
                int u = __shfl_up_sync(0xFFFFFFFFu, ex, o);
                if (lane >= o) ex += u;
            }
            if (lane == 31) g_off[NN] = ex;
            sh[lane] = ex - v;
        }
        __syncthreads();
        int carry = sh[w];
        for (int k = 0; k < 64; k++) {
            int v = g_deg[base + k * 32 + lane];
            int inc = v;
            #pragma unroll
            for (int o = 1; o < 32; o <<= 1) {
                int u = __shfl_up_sync(0xFFFFFFFFu, inc, o);
                if (lane >= o) inc += u;
            }
            int ex = carry + inc - v;
            g_off[base + k * 32 + lane] = ex;
            g_cur[base + k * 32 + lane] = ex;
            carry += __shfl_sync(0xFFFFFFFFu, inc, 31);
        }
    } else {
        int a0 = g_gcnt[2 * t], a1 = g_gcnt[2 * t + 1];
        int s = a0 + a1;
        sh[t] = s;
        __syncthreads();
        for (int d = 1; d < 1024; d <<= 1) {
            int v = (t >= d) ? sh[t - d] : 0;
            __syncthreads();
            sh[t] += v;
            __syncthreads();
        }
        int off = sh[t] - s;
        g_gstart[2 * t] = off;
        g_gstart[2 * t + 1] = off + a0;
    }
}

// ---------------------- weight splitting (all in one launch) ----------------
__device__ __forceinline__ void splitw_seg(const float* W, __nv_bfloat16* oh,
                                           __nv_bfloat16* ol, int K, int Nn, int Kp) {
    GSTRIDE(idx, Nn * Kp) {
        int n = idx / Kp, k = idx % Kp;
        float v = (k < K) ? W[(size_t)k * Nn + n] : 0.f;
        __nv_bfloat16 hi, lo;
        split_bf16(v, hi, lo);
        oh[idx] = hi;
        ol[idx] = lo;
    }
}
__global__ void k_splitw_all(const float* __restrict__ gW1, const float* __restrict__ gW2,
                             const float* __restrict__ vW1, const float* __restrict__ vW2,
                             const float* __restrict__ Wp1) {
    int y = blockIdx.y;
    if (y < LL) {
        splitw_seg(gW1 + (size_t)y * HH * H2, g_gW1h + (size_t)y * H2 * KP1,
                   g_gW1l + (size_t)y * H2 * KP1, HH, H2, KP1);
    } else if (y < 2 * LL) {
        int l = y - LL;
        splitw_seg(gW2 + (size_t)l * H2 * HH, g_gW2h + (size_t)l * HH * KP2,
                   g_gW2l + (size_t)l * HH * KP2, H2, HH, KP2);
    } else if (y < 2 * LL + 4) {
        int l = y - 2 * LL;
        splitw_seg(vW1 + (size_t)l * HH * H2, g_vW1h + (size_t)l * H2 * KP1,
                   g_vW1l + (size_t)l * H2 * KP1, HH, H2, KP1);
    } else if (y < 2 * LL + 8) {
        int l = y - 2 * LL - 4;
        splitw_seg(vW2 + (size_t)l * H2 * HH, g_vW2h + (size_t)l * HH * KP2,
                   g_vW2l + (size_t)l * HH * KP2, H2, HH, KP2);
    } else {
        splitw_seg(Wp1, g_Wph, g_Wpl, DGC, H2, KPP);
    }
}

// ---------------------- mma.sync GEMM (two-region merged, 2-stage) ----------
#define RS_B 80
#define A_OFF 0
#define AL_OFF 10240
#define BH_OFF 20480
#define BL_OFF 30720
#define STAGE 40960
#define SMEMSZ (2 * STAGE)

#define MMA(c, a, b0v, b1v) \
    asm volatile("mma.sync.aligned.m16n8k16.row.col.f32.bf16.bf16.f32 " \
                 "{%0,%1,%2,%3},{%4,%5,%6,%7},{%8,%9},{%0,%1,%2,%3};" \
                 : "+f"((c)[0]), "+f"((c)[1]), "+f"((c)[2]), "+f"((c)[3]) \
                 : "r"((a)[0]), "r"((a)[1]), "r"((a)[2]), "r"((a)[3]), \
                   "r"(b0v), "r"(b1v))
#define CP16(dst, src) \
    asm volatile("cp.async.cg.shared.global [%0], [%1], 16;" :: "r"(dst), "l"(src))
#define CPCOMMIT asm volatile("cp.async.commit_group;" ::: "memory")
#define CPWAIT1 asm volatile("cp.async.wait_group 1;" ::: "memory")
#define CPWAIT0 asm volatile("cp.async.wait_group 0;" ::: "memory")

__device__ __forceinline__ void ldsm4(uint32_t& r0, uint32_t& r1, uint32_t& r2,
                                      uint32_t& r3, uint32_t a) {
    asm volatile("ldmatrix.sync.aligned.m8n8.x4.shared.b16 {%0,%1,%2,%3}, [%4];"
                 : "=r"(r0), "=r"(r1), "=r"(r2), "=r"(r3) : "r"(a));
}

template <int CFG>
__global__ void __launch_bounds__(256, 2)
k_mma(const __nv_bfloat16* __restrict__ Ah1, const __nv_bfloat16* __restrict__ Al1,
      const __nv_bfloat16* __restrict__ Bh1, const __nv_bfloat16* __restrict__ Bl1,
      const float* __restrict__ bias1, float* __restrict__ F1,
      __nv_bfloat16* __restrict__ H1, __nv_bfloat16* __restrict__ L1,
      const __nv_bfloat16* __restrict__ Ah2, const __nv_bfloat16* __restrict__ Al2,
      const __nv_bfloat16* __restrict__ Bh2, const __nv_bfloat16* __restrict__ Bl2,
      const float* __restrict__ bias2, float* __restrict__ F2,
      __nv_bfloat16* __restrict__ H2o, __nv_bfloat16* __restrict__ L2o,
      int My1, int K, int N, int ldc) {
    extern __shared__ __align__(16) char sm[];
    const uint32_t sb = smem_u32(sm);
    const int tid = threadIdx.x, wid = tid >> 5, lane = tid & 31;
    const bool rg2 = (int)blockIdx.y >= My1;
    const int by = rg2 ? (int)blockIdx.y - My1 : (int)blockIdx.y;
    const __nv_bfloat16* Ah = rg2 ? Ah2 : Ah1;
    const __nv_bfloat16* Al = rg2 ? Al2 : Al1;
    const __nv_bfloat16* Bh = rg2 ? Bh2 : Bh1;
    const __nv_bfloat16* Bl = rg2 ? Bl2 : Bl1;
    const float* bias = rg2 ? bias2 : bias1;
    const int bm = by << 7, n0 = (int)blockIdx.x << 7;
    const int NC = K >> 5;
    const int nv = (N - n0) < 128 ? (N - n0) : 128;

    auto load_stage = [&](int c, int s) {
        char* bufc = sm + s * STAGE;
        uint32_t bufu = sb + s * STAGE;
        const int kh0 = c << 5;
        #pragma unroll
        for (int u = 0; u < 2; u++) {
            int idx = tid + (u << 8);
            int r = idx >> 2, kc = idx & 3;
            uint32_t doff = (uint32_t)r * RS_B + ((uint32_t)kc << 4);
            size_t go = (size_t)(bm + r) * K + kh0 + (kc << 3);
            CP16(bufu + A_OFF + doff, Ah + go);
            CP16(bufu + AL_OFF + doff, Al + go);
        }
        #pragma unroll
        for (int u = 0; u < 2; u++) {
            int idx = tid + (u << 8);
            int r = idx >> 2, kc = idx & 3;
            uint32_t doff = (uint32_t)r * RS_B + ((uint32_t)kc << 4);
            int gn = n0 + r;
            if (gn < N) {
                size_t go = (size_t)gn * K + kh0 + (kc << 3);
                CP16(bufu + BH_OFF + doff, Bh + go);
                CP16(bufu + BL_OFF + doff, Bl + go);
            } else {
                uint4 z = make_uint4(0, 0, 0, 0);
                *(uint4*)(bufc + BH_OFF + doff) = z;
                *(uint4*)(bufc + BL_OFF + doff) = z;
            }
        }
    };

    const int wm = (wid & 3) << 5, wn = (wid >> 2) << 6;
    const int wrem = nv - wn;
    const uint32_t aBase = (uint32_t)((wm + (lane & 15)) * RS_B + ((lane >> 4) << 4));
    const uint32_t bBase = (uint32_t)((wn + ((lane >> 4) << 3) + (lane & 7)) * RS_B +
                                      (((lane >> 3) & 1) << 4));

    float acc[2][8][4];
    #pragma unroll
    for (int a = 0; a < 2; a++)
        #pragma unroll
        for (int b = 0; b < 8; b++)
            #pragma unroll
            for (int q = 0; q < 4; q++) acc[a][b][q] = 0.f;

    load_stage(0, 0);
    CPCOMMIT;
    if (NC > 1) load_stage(1, 1);
    CPCOMMIT;

    for (int c = 0; c < NC; c++) {
        if (c == NC - 1) { CPWAIT0; } else { CPWAIT1; }
        __syncthreads();
        uint32_t st = sb + (c & 1) * STAGE;
        if (wrem > 0) {
            #pragma unroll
            for (int kb = 0; kb < 64; kb += 32) {
                uint32_t ah0[4], ah1[4], al0[4], al1[4];
                ldsm4(ah0[0], ah0[1], ah0[2], ah0[3], st + A_OFF + aBase + kb);
                ldsm4(ah1[0], ah1[1], ah1[2], ah1[3], st + A_OFF + aBase + 16 * RS_B + kb);
                ldsm4(al0[0], al0[1], al0[2], al0[3], st + AL_OFF + aBase + kb);
                ldsm4(al1[0], al1[1], al1[2], al1[3], st + AL_OFF + aBase + 16 * RS_B + kb);
                #pragma unroll
                for (int nt = 0; nt < 4; nt++) {
                    if (nt * 16 < wrem) {
                        uint32_t bh[4], bl[4];
                        ldsm4(bh[0], bh[1], bh[2], bh[3],
                              st + BH_OFF + bBase + nt * 16 * RS_B + kb);
                        ldsm4(bl[0], bl[1], bl[2], bl[3],
                              st + BL_OFF + bBase + nt * 16 * RS_B + kb);
                        MMA(acc[0][2 * nt],     ah0, bh[0], bh[1]);
                        MMA(acc[0][2 * nt + 1], ah0, bh[2], bh[3]);
                        MMA(acc[1][2 * nt],     ah1, bh[0], bh[1]);
                        MMA(acc[1][2 * nt + 1], ah1, bh[2], bh[3]);
                        MMA(acc[0][2 * nt],     ah0, bl[0], bl[1]);
                        MMA(acc[0][2 * nt + 1], ah0, bl[2], bl[3]);
                        MMA(acc[1][2 * nt],     ah1, bl[0], bl[1]);
                        MMA(acc[1][2 * nt + 1], ah1, bl[2], bl[3]);
                        MMA(acc[0][2 * nt],     al0, bh[0], bh[1]);
                        MMA(acc[0][2 * nt + 1], al0, bh[2], bh[3]);
                        MMA(acc[1][2 * nt],     al1, bh[0], bh[1]);
                        MMA(acc[1][2 * nt + 1], al1, bh[2], bh[3]);
                    }
                }
            }
        }
        __syncthreads();
        if (c + 2 < NC) {
            load_stage(c + 2, c & 1);
            CPCOMMIT;
        }
    }

    // epilogue
    const int r0 = bm + wm + (lane >> 2);
    const int cbl = n0 + wn + ((lane & 3) << 1);
    if (CFG == 0) {
        __nv_bfloat16* Ch = rg2 ? H2o : H1;
        __nv_bfloat16* Cl = rg2 ? L2o : L1;
        #pragma unroll
        for (int mt = 0; mt < 2; mt++) {
            #pragma unroll
            for (int nf = 0; nf < 8; nf++) {
                int col = cbl + (nf << 3);
                if (col >= N) continue;
                float2 bv = *(const float2*)(bias + col);
                int row = r0 + (mt << 4);
                float v0 = fmaxf(acc[mt][nf][0] + bv.x, 0.f);
                float v1 = fmaxf(acc[mt][nf][1] + bv.y, 0.f);
                float v2 = fmaxf(acc[mt][nf][2] + bv.x, 0.f);
                float v3 = fmaxf(acc[mt][nf][3] + bv.y, 0.f);
                __nv_bfloat16 h0, l0, h1, l1;
                split_bf16(v0, h0, l0);
                split_bf16(v1, h1, l1);
                size_t w0 = ((size_t)row * ldc + col) >> 1;
                ((uint32_t*)Ch)[w0] = pack2(h0, h1);
                ((uint32_t*)Cl)[w0] = pack2(l0, l1);
                split_bf16(v2, h0, l0);
                split_bf16(v3, h1, l1);
                size_t w1 = ((size_t)(row + 8) * ldc + col) >> 1;
                ((uint32_t*)Ch)[w1] = pack2(h0, h1);
                ((uint32_t*)Cl)[w1] = pack2(l0, l1);
            }
        }
    } else if (CFG == 1) {
        if (!rg2) {
            #pragma unroll
            for (int mt = 0; mt < 2; mt++) {
                #pragma unroll
                for (int nf = 0; nf < 8; nf++) {
                    int col = cbl + (nf << 3);
                    if (col >= N) continue;
                    float2 bv = *(const float2*)(bias + col);
                    int row = r0 + (mt << 4);
                    *(float2*)(F1 + (size_t)row * ldc + col) =
                        make_float2(acc[mt][nf][0] + bv.x, acc[mt][nf][1] + bv.y);
                    *(float2*)(F1 + (size_t)(row + 8) * ldc + col) =
                        make_float2(acc[mt][nf][2] + bv.x, acc[mt][nf][3] + bv.y);
                }
            }
            #pragma unroll
            for (int nf = 0; nf < 8; nf++) {
                int col = cbl + (nf << 3);
                bool ok = col < N;
                float2 bv = ok ? *(const float2*)(bias + col) : make_float2(0.f, 0.f);
                float s0 = 0.f, q0 = 0.f, s1 = 0.f, q1 = 0.f;
                #pragma unroll
                for (int mt = 0; mt < 2; mt++) {
                    float v0 = acc[mt][nf][0] + bv.x, v1 = acc[mt][nf][1] + bv.y;
                    float v2 = acc[mt][nf][2] + bv.x, v3 = acc[mt][nf][3] + bv.y;
                    s0 += v0 + v2; q0 += v0 * v0 + v2 * v2;
                    s1 += v1 + v3; q1 += v1 * v1 + v3 * v3;
                }
                #pragma unroll
                for (int o = 4; o < 32; o <<= 1) {
                    s0 += __shfl_xor_sync(0xFFFFFFFFu, s0, o);
                    q0 += __shfl_xor_sync(0xFFFFFFFFu, q0, o);
                    s1 += __shfl_xor_sync(0xFFFFFFFFu, s1, o);
                    q1 += __shfl_xor_sync(0xFFFFFFFFu, q1, o);
                }
                if (lane < 4 && ok) {
                    atomicAdd(&g_stats[col], s0);
                    atomicAdd(&g_stats[col + 1], s1);
                    atomicAdd(&g_stats[HH + col], q0);
                    atomicAdd(&g_stats[HH + col + 1], q1);
                }
            }
        } else {
            #pragma unroll
            for (int mt = 0; mt < 2; mt++) {
                #pragma unroll
                for (int nf = 0; nf < 8; nf++) {
                    int col = cbl + (nf << 3);
                    if (col >= N) continue;
                    float2 bv = *(const float2*)(bias + col);
                    int row = r0 + (mt << 4);
                    float v0 = fmaxf(acc[mt][nf][0] + bv.x, 0.f);
                    float v1 = fmaxf(acc[mt][nf][1] + bv.y, 0.f);
                    float v2 = fmaxf(acc[mt][nf][2] + bv.x, 0.f);
                    float v3 = fmaxf(acc[mt][nf][3] + bv.y, 0.f);
                    float2 o0 = *(const float2*)(F2 + (size_t)row * ldc + col);
                    float2 o1 = *(const float2*)(F2 + (size_t)(row + 8) * ldc + col);
                    *(float2*)(F2 + (size_t)row * ldc + col) =
                        make_float2(o0.x + v0, o0.y + v1);
                    *(float2*)(F2 + (size_t)(row + 8) * ldc + col) =
                        make_float2(o1.x + v2, o1.y + v3);
                }
            }
        }
    } else {
        float s[4] = {0.f, 0.f, 0.f, 0.f};
        #pragma unroll
        for (int mt = 0; mt < 2; mt++) {
            #pragma unroll
            for (int nf = 0; nf < 8; nf++) {
                int col = cbl + (nf << 3);
                if (col < N) {
                    float2 bv = *(const float2*)(bias + col);
                    float w0 = bias2[col], w1 = bias2[col + 1];
                    float v0 = fmaxf(acc[mt][nf][0] + bv.x, 0.f);
                    float v1 = fmaxf(acc[mt][nf][1] + bv.y, 0.f);
                    float v2 = fmaxf(acc[mt][nf][2] + bv.x, 0.f);
                    float v3 = fmaxf(acc[mt][nf][3] + bv.y, 0.f);
                    s[2 * mt] += v0 * w0 + v1 * w1;
                    s[2 * mt + 1] += v2 * w0 + v3 * w1;
                }
            }
        }
        #pragma unroll
        for (int q = 0; q < 4; q++) {
            s[q] += __shfl_xor_sync(0xFFFFFFFFu, s[q], 1);
            s[q] += __shfl_xor_sync(0xFFFFFFFFu, s[q], 2);
        }
        if ((lane & 3) == 0) {
            atomicAdd(&F2[r0], s[0]);
            atomicAdd(&F2[r0 + 8], s[1]);
            atomicAdd(&F2[r0 + 16], s[2]);
            atomicAdd(&F2[r0 + 24], s[3]);
        }
    }
}

// --------- BN apply (scalar) + hv production for the next layer -------------
__global__ void k_bnapply(const float* __restrict__ scale, const float* __restrict__ bias,
                          const int* __restrict__ batch, int vnl) {
    int j = threadIdx.x;
    if (j >= HH) return;
    const float invN = 1.f / (float)NN;
    float m = g_stats[j] * invN;
    float var = g_stats[HH + j] * invN - m * m;
    float co = rsqrtf(var + 1e-5f) * scale[j];
    float bi = bias[j];
    #pragma unroll
    for (int r = 0; r < 4; r++) {
        int node = blockIdx.x * 4 + r;
        size_t o = (size_t)node * HH + j;
        float z = (g_z2[o] - m) * co + bi;
        if (vnl) z = fmaxf(z, 0.f);
        float hn = g_h[o] + z;
        g_h[o] = hn;
        if (vnl) g_hv[o] = hn + g_vn[(size_t)batch[node] * HH + j];
    }
}

// ---------------------------------------------------------------------------
static inline int nblk(long long work, int t) { return (int)((work + t - 1) / t); }

extern "C" void kernel_launch(void* const* d_in, const int* in_sizes, int n_in,
                              void* d_out, int out_size) {
    const void* ord[21];
    int p = 0;
    const int* edge = nullptr;
    const int* batch = nullptr;
    for (int i = 0; i < n_in; i++) {
        if (in_sizes[i] == 2 * EE) edge = (const int*)d_in[i];
        else if (in_sizes[i] == NN) batch = (const int*)d_in[i];
        else if (p < 21) ord[p++] = d_in[i];
    }
    const float* x        = (const float*)ord[0];
    const float* morgan   = (const float*)ord[1];
    const float* maccs    = (const float*)ord[2];
    const float* W_emb    = (const float*)ord[3];
    const float* b_emb    = (const float*)ord[4];
    const float* gin_W1   = (const float*)ord[5];
    const float* gin_b1   = (const float*)ord[6];
    const float* gin_W2   = (const float*)ord[7];
    const float* gin_b2   = (const float*)ord[8];
    const float* bn_scale = (const float*)ord[9];
    const float* bn_bias  = (const float*)ord[10];
    const float* eps      = (const float*)ord[11];
    const float* vn0      = (const float*)ord[12];
    const float* vn_W1    = (const float*)ord[13];
    const float* vn_b1    = (const float*)ord[14];
    const float* vn_W2    = (const float*)ord[15];
    const float* vn_b2    = (const float*)ord[16];
    const float* Wp1      = (const float*)ord[17];
    const float* bp1      = (const float*)ord[18];
    const float* Wp2      = (const float*)ord[19];
    const float* bp2      = (const float*)ord[20];
    const int* src = edge;
    const int* dst = edge + EE;
    float* out = (float*)d_out;

    float *pz2, *pvn;
    __nv_bfloat16 *pzinh, *pzinl, *pt1h, *pt1l, *pvth, *pvtl, *pvhh, *pvhl, *phrh, *phrl;
    __nv_bfloat16 *pgW1h, *pgW1l, *pgW2h, *pgW2l, *pvW1h, *pvW1l, *pvW2h, *pvW2l, *pWph, *pWpl;
    cudaGetSymbolAddress((void**)&pz2, g_z2);
    cudaGetSymbolAddress((void**)&pvn, g_vn);
    cudaGetSymbolAddress((void**)&pzinh, g_zinh);
    cudaGetSymbolAddress((void**)&pzinl, g_zinl);
    cudaGetSymbolAddress((void**)&pt1h, g_t1h);
    cudaGetSymbolAddress((void**)&pt1l, g_t1l);
    cudaGetSymbolAddress((void**)&pvth, g_vth);
    cudaGetSymbolAddress((void**)&pvtl, g_vtl);
    cudaGetSymbolAddress((void**)&pvhh, g_vhh);
    cudaGetSymbolAddress((void**)&pvhl, g_vhl);
    cudaGetSymbolAddress((void**)&phrh, g_hreph);
    cudaGetSymbolAddress((void**)&phrl, g_hrepl);
    cudaGetSymbolAddress((void**)&pgW1h, g_gW1h);
    cudaGetSymbolAddress((void**)&pgW1l, g_gW1l);
    cudaGetSymbolAddress((void**)&pgW2h, g_gW2h);
    cudaGetSymbolAddress((void**)&pgW2l, g_gW2l);
    cudaGetSymbolAddress((void**)&pvW1h, g_vW1h);
    cudaGetSymbolAddress((void**)&pvW1l, g_vW1l);
    cudaGetSymbolAddress((void**)&pvW2h, g_vW2h);
    cudaGetSymbolAddress((void**)&pvW2l, g_vW2l);
    cudaGetSymbolAddress((void**)&pWph, g_Wph);
    cudaGetSymbolAddress((void**)&pWpl, g_Wpl);

    cudaFuncSetAttribute(k_mma<0>, cudaFuncAttributeMaxDynamicSharedMemorySize, SMEMSZ);
    cudaFuncSetAttribute(k_mma<1>, cudaFuncAttributeMaxDynamicSharedMemorySize, SMEMSZ);
    cudaFuncSetAttribute(k_mma<2>, cudaFuncAttributeMaxDynamicSharedMemorySize, SMEMSZ);

    const int T = 256;

    // setup
    k_embed<<<NN / 4, 320>>>(x, W_emb, b_emb, vn0);
    k_setup<<<nblk(NN + GG + GG * HH, T), T>>>(vn0, bp2, out);
    k_splitw_all<<<dim3(512, 19), T>>>(gin_W1, gin_W2, vn_W1, vn_W2, Wp1);
    k_hist<<<nblk(EE, T), T>>>(dst, batch);
    k_scan_both<<<2, 1024>>>();
    k_scatter<<<nblk(EE, T), T>>>(src, dst);

    for (int l = 0; l < LL; l++) {
        bool vnl = l < LL - 1;
        int vtb = vnl ? GG / 8 : 0;
        k_gather<<<vtb + NN / 8, 256>>>(eps, l, vtb);

        int gy = 512 + (vnl ? 16 : 0);
        k_mma<0><<<dim3(5, gy), 256, SMEMSZ>>>(
            pzinh, pzinl,
            pgW1h + (size_t)l * H2 * KP1, pgW1l + (size_t)l * H2 * KP1,
            gin_b1 + (size_t)l * H2, nullptr, pt1h, pt1l,
            pvth, pvtl,
            vnl ? pvW1h + (size_t)l * H2 * KP1 : nullptr,
            vnl ? pvW1l + (size_t)l * H2 * KP1 : nullptr,
            vnl ? vn_b1 + (size_t)l * H2 : nullptr, nullptr, pvhh, pvhl,
            512, KP1, H2, KP2);
        k_mma<1><<<dim3(3, gy), 256, SMEMSZ>>>(
            pt1h, pt1l,
            pgW2h + (size_t)l * HH * KP2, pgW2l + (size_t)l * HH * KP2,
            gin_b2 + (size_t)l * HH, pz2, nullptr, nullptr,
            pvhh, pvhl,
            vnl ? pvW2h + (size_t)l * HH * KP2 : nullptr,
            vnl ? pvW2l + (size_t)l * HH * KP2 : nullptr,
            vnl ? vn_b2 + (size_t)l * HH : nullptr, pvn, nullptr, nullptr,
            512, KP2, HH, HH);

        k_bnapply<<<NN / 4, 320>>>(bn_scale + (size_t)l * HH,
                                   bn_bias + (size_t)l * HH, batch, vnl ? 1 : 0);
    }

    k_poolassemble<<<GG / 8, 256>>>(morgan, maccs);
    k_mma<2><<<dim3(5, 16), 256, SMEMSZ>>>(
        phrh, phrl, pWph, pWpl, bp1, nullptr, nullptr, nullptr,
        nullptr, nullptr, nullptr, nullptr, Wp2, out, nullptr, nullptr,
        16, KPP, H2, H2);
}

// round 17
// speedup vs baseline: 1.0011x; 1.0011x over previous
#include <cuda_runtime.h>
#include <cuda_bf16.h>
#include <cstdint>
#include <cstddef>

#define NN 65536
#define EE 262144
#define GG 2048
#define DIN 9
#define HH 300
#define H2 600
#define FF 32
#define LL 5
#define KP1 320
#define KP2 608
#define KPP 1536
#define DGC 1523

// ---------------- scratch (device globals; no allocation allowed) ----------
static __device__ __align__(16) float g_h[(size_t)NN * HH];
static __device__ __align__(16) float g_hv[(size_t)NN * HH];
static __device__ __align__(16) float g_z2[(size_t)NN * HH];
static __device__ __align__(16) float g_vn[(size_t)GG * HH];
static __device__ __align__(16) float g_stats[2 * HH];
static __device__ int g_deg[NN];
static __device__ int g_off[NN + 1];
static __device__ int g_cur[NN];
static __device__ int g_csr[EE];
static __device__ int g_gcnt[GG];
static __device__ int g_gstart[GG];

// split bf16 activation buffers (padded K strides)
static __device__ __align__(16) __nv_bfloat16 g_zinh[(size_t)NN * KP1];
static __device__ __align__(16) __nv_bfloat16 g_zinl[(size_t)NN * KP1];
static __device__ __align__(16) __nv_bfloat16 g_t1h[(size_t)NN * KP2];
static __device__ __align__(16) __nv_bfloat16 g_t1l[(size_t)NN * KP2];
static __device__ __align__(16) __nv_bfloat16 g_vth[(size_t)GG * KP1];
static __device__ __align__(16) __nv_bfloat16 g_vtl[(size_t)GG * KP1];
static __device__ __align__(16) __nv_bfloat16 g_vhh[(size_t)GG * KP2];
static __device__ __align__(16) __nv_bfloat16 g_vhl[(size_t)GG * KP2];
static __device__ __align__(16) __nv_bfloat16 g_hreph[(size_t)GG * KPP];
static __device__ __align__(16) __nv_bfloat16 g_hrepl[(size_t)GG * KPP];
// split transposed weights [L][N][Kp]
static __device__ __align__(16) __nv_bfloat16 g_gW1h[(size_t)LL * H2 * KP1];
static __device__ __align__(16) __nv_bfloat16 g_gW1l[(size_t)LL * H2 * KP1];
static __device__ __align__(16) __nv_bfloat16 g_gW2h[(size_t)LL * HH * KP2];
static __device__ __align__(16) __nv_bfloat16 g_gW2l[(size_t)LL * HH * KP2];
static __device__ __align__(16) __nv_bfloat16 g_vW1h[(size_t)(LL - 1) * H2 * KP1];
static __device__ __align__(16) __nv_bfloat16 g_vW1l[(size_t)(LL - 1) * H2 * KP1];
static __device__ __align__(16) __nv_bfloat16 g_vW2h[(size_t)(LL - 1) * HH * KP2];
static __device__ __align__(16) __nv_bfloat16 g_vW2l[(size_t)(LL - 1) * HH * KP2];
static __device__ __align__(16) __nv_bfloat16 g_Wph[(size_t)H2 * KPP];
static __device__ __align__(16) __nv_bfloat16 g_Wpl[(size_t)H2 * KPP];

#define GSTRIDE(i, n) for (int i = blockIdx.x * blockDim.x + threadIdx.x; \
                           i < (int)(n); i += gridDim.x * blockDim.x)

__device__ __forceinline__ void split_bf16(float v, __nv_bfloat16& hi, __nv_bfloat16& lo) {
    hi = __float2bfloat16_rn(v);
    lo = __float2bfloat16_rn(v - __bfloat162float(hi));
}
__device__ __forceinline__ uint32_t pack2(__nv_bfloat16 a, __nv_bfloat16 b) {
    __nv_bfloat162 t; t.x = a; t.y = b;
    return *(uint32_t*)&t;
}
__device__ __forceinline__ void split_store4(float4 v, __nv_bfloat16* ph, __nv_bfloat16* pl) {
    __nv_bfloat16 h0, l0, h1, l1, h2, l2, h3, l3;
    split_bf16(v.x, h0, l0);
    split_bf16(v.y, h1, l1);
    split_bf16(v.z, h2, l2);
    split_bf16(v.w, h3, l3);
    *(uint2*)ph = make_uint2(pack2(h0, h1), pack2(h2, h3));
    *(uint2*)pl = make_uint2(pack2(l0, l1), pack2(l2, l3));
}
__device__ __forceinline__ uint32_t smem_u32(const void* p) {
    uint32_t a;
    asm("{ .reg .u64 t; cvta.to.shared.u64 t, %1; cvt.u32.u64 %0, t; }" : "=r"(a) : "l"(p));
    return a;
}

// ------------------------- small kernels -----------------------------------
// embed: h = x @ W_emb + b; hv(layer 0) = h + vn0[j]
__global__ void k_embed(const float* __restrict__ x, const float* __restrict__ W,
                        const float* __restrict__ b, const float* __restrict__ vn0) {
    int j = threadIdx.x;
    if (j >= HH) return;
    float bj = b[j];
    float v0 = vn0[j];
    #pragma unroll
    for (int r = 0; r < 4; r++) {
        int node = blockIdx.x * 4 + r;
        const float* xr = x + (size_t)node * DIN;
        float acc = bj;
        #pragma unroll
        for (int k = 0; k < DIN; k++) acc += xr[k] * W[k * HH + j];
        g_h[(size_t)node * HH + j] = acc;
        g_hv[(size_t)node * HH + j] = acc + v0;
    }
}

// fused setup: deg/gcnt zero, out init, pad zero, coalesced vn init
__global__ void k_setup(const float* __restrict__ vn0, const float* __restrict__ bp2,
                        float* __restrict__ out) {
    GSTRIDE(i, NN + GG + GG * HH) {
        if (i < NN) {
            g_deg[i] = 0;
            #pragma unroll
            for (int q = 0; q < 5; q++) {
                *(uint2*)(g_zinh + (size_t)i * KP1 + HH + q * 4) = make_uint2(0, 0);
                *(uint2*)(g_zinl + (size_t)i * KP1 + HH + q * 4) = make_uint2(0, 0);
            }
            *(uint4*)(g_t1h + (size_t)i * KP2 + H2) = make_uint4(0, 0, 0, 0);
            *(uint4*)(g_t1l + (size_t)i * KP2 + H2) = make_uint4(0, 0, 0, 0);
        } else if (i < NN + GG) {
            int r = i - NN;
            g_gcnt[r] = 0;
            out[r] = bp2[0];
            #pragma unroll
            for (int q = 0; q < 5; q++) {
                *(uint2*)(g_vth + (size_t)r * KP1 + HH + q * 4) = make_uint2(0, 0);
                *(uint2*)(g_vtl + (size_t)r * KP1 + HH + q * 4) = make_uint2(0, 0);
            }
            *(uint4*)(g_vhh + (size_t)r * KP2 + H2) = make_uint4(0, 0, 0, 0);
            *(uint4*)(g_vhl + (size_t)r * KP2 + H2) = make_uint4(0, 0, 0, 0);
        } else {
            int idx = i - NN - GG;
            g_vn[idx] = vn0[idx % HH];
        }
    }
}

// fused: blocks [0, vtblocks): vt gather (longest first);
//        blocks [vtblocks, +NN/8): zin gather (+stats zero on first zin block).
// zin[n] = (1+eps)*hv[n] + sum_nb hv[s];  vt[g] = vn[g] + sum_{i in g} hv[i]
__global__ void __launch_bounds__(256, 6) k_gather(const float* __restrict__ eps, int l,
                                                   int vtblocks) {
    int w = threadIdx.x >> 5, lane = threadIdx.x & 31;
    const float4* hv4 = (const float4*)g_hv;
    if ((int)blockIdx.x < vtblocks) {
        int g = ((int)blockIdx.x << 3) + w;
        int s0 = g_gstart[g], c = g_gcnt[g];
        const float4* vn4 = (const float4*)g_vn;
        float4 acc[3];
        #pragma unroll
        for (int q = 0; q < 3; q++) {
            int idx = lane + (q << 5);
            if (idx < 75) acc[q] = vn4[(size_t)g * 75 + idx];
        }
        for (int i = 0; i < c; i++) {
            size_t row = (size_t)(s0 + i) * 75;
            #pragma unroll
            for (int q = 0; q < 3; q++) {
                int idx = lane + (q << 5);
                if (idx < 75) {
                    float4 a = hv4[row + idx];
                    acc[q].x += a.x; acc[q].y += a.y; acc[q].z += a.z; acc[q].w += a.w;
                }
            }
        }
        #pragma unroll
        for (int q = 0; q < 3; q++) {
            int idx = lane + (q << 5);
            if (idx < 75)
                split_store4(acc[q], g_vth + (size_t)g * KP1 + idx * 4,
                             g_vtl + (size_t)g * KP1 + idx * 4);
        }
    } else {
        int zb = (int)blockIdx.x - vtblocks;
        if (zb == 0) {
            for (int i = threadIdx.x; i < 2 * HH; i += 256) g_stats[i] = 0.f;
        }
        int n = (zb << 3) + w;
        float e1 = 1.f + eps[l];
        float4 acc[3];
        #pragma unroll
        for (int q = 0; q < 3; q++) {
            int idx = lane + (q << 5);
            if (idx < 75) {
                float4 a = hv4[(size_t)n * 75 + idx];
                acc[q] = make_float4(e1 * a.x, e1 * a.y, e1 * a.z, e1 * a.w);
            }
        }
        int e0 = g_off[n], e1i = g_off[n + 1];
        int s = (e0 < e1i) ? g_csr[e0] : 0;
        for (int e = e0; e < e1i; e++) {
            int s_next = (e + 1 < e1i) ? g_csr[e + 1] : 0;
            size_t row = (size_t)s * 75;
            #pragma unroll
            for (int q = 0; q < 3; q++) {
                int idx = lane + (q << 5);
                if (idx < 75) {
                    float4 a = hv4[row + idx];
                    acc[q].x += a.x; acc[q].y += a.y; acc[q].z += a.z; acc[q].w += a.w;
                }
            }
            s = s_next;
        }
        #pragma unroll
        for (int q = 0; q < 3; q++) {
            int idx = lane + (q << 5);
            if (idx < 75)
                split_store4(acc[q], g_zinh + (size_t)n * KP1 + idx * 4,
                             g_zinl + (size_t)n * KP1 + idx * 4);
        }
    }
}

// fused pool + assemble
__global__ void __launch_bounds__(256, 6) k_poolassemble(const float* __restrict__ morgan,
                                                         const float* __restrict__ maccs) {
    int w = threadIdx.x >> 5, lane = threadIdx.x & 31;
    int g = (blockIdx.x << 3) + w;
    int s0 = g_gstart[g], c = g_gcnt[g];
    const float4* h4 = (const float4*)g_h;
    float4 acc[3];
    #pragma unroll
    for (int q = 0; q < 3; q++) acc[q] = make_float4(0.f, 0.f, 0.f, 0.f);
    for (int i = 0; i < c; i++) {
        size_t row = (size_t)(s0 + i) * 75;
        #pragma unroll
        for (int q = 0; q < 3; q++) {
            int idx = lane + (q << 5);
            if (idx < 75) {
                float4 a = h4[row + idx];
                acc[q].x += a.x; acc[q].y += a.y; acc[q].z += a.z; acc[q].w += a.w;
            }
        }
    }
    float denom = fmaxf((float)c, 1.f);
    __nv_bfloat16* rh = g_hreph + (size_t)g * KPP;
    __nv_bfloat16* rl = g_hrepl + (size_t)g * KPP;
    #pragma unroll
    for (int q = 0; q < 3; q++) {
        int idx = lane + (q << 5);
        if (idx < 75) {
            float4 v = make_float4(acc[q].x / denom, acc[q].y / denom,
                                   acc[q].z / denom, acc[q].w / denom);
            split_store4(v, rh + idx * 4, rl + idx * 4);
        }
    }
    {
        int f = lane;
        int cf = (f < c) ? ((c - 1 - f) / FF + 1) : 0;
        float v = (float)cf / denom;
        __nv_bfloat16 hi, lo;
        split_bf16(v, hi, lo);
        rh[HH + f] = hi;
        rl[HH + f] = lo;
    }
    const float* mg = morgan + (size_t)g * 1024;
    for (int j = lane; j < 1024; j += 32) {
        __nv_bfloat16 hi, lo;
        split_bf16(mg[j], hi, lo);
        rh[HH + FF + j] = hi;
        rl[HH + FF + j] = lo;
    }
    const float* mc = maccs + (size_t)g * 167;
    for (int j = lane; j < 167; j += 32) {
        __nv_bfloat16 hi, lo;
        split_bf16(mc[j], hi, lo);
        rh[HH + FF + 1024 + j] = hi;
        rl[HH + FF + 1024 + j] = lo;
    }
    if (lane < KPP - DGC) {
        __nv_bfloat16 z = __float2bfloat16_rn(0.f);
        rh[DGC + lane] = z;
        rl[DGC + lane] = z;
    }
}

// ---------------------- CSR / segment build --------------------------------
__global__ void k_hist(const int* __restrict__ dst, const int* __restrict__ batch) {
    GSTRIDE(e, EE) atomicAdd(&g_deg[dst[e]], 1);
    GSTRIDE(i, NN) atomicAdd(&g_gcnt[batch[i]], 1);
}
__global__ void k_scatter(const int* __restrict__ src, const int* __restrict__ dst) {
    GSTRIDE(e, EE) {
        int pos = atomicAdd(&g_cur[dst[e]], 1);
        g_csr[pos] = src[e];
    }
}
__global__ void __launch_bounds__(1024) k_scan_both() {
    __shared__ int sh[1024];
    int t = threadIdx.x, w = t >> 5, lane = t & 31;
    if (blockIdx.x == 0) {
        int base = w * 2048;
        int s = 0;
        for (int k = 0; k < 64; k++) s += g_deg[base + k * 32 + lane];
        #pragma unroll
        for (int o = 16; o; o >>= 1) s += __shfl_xor_sync(0xFFFFFFFFu, s, o);
        if (!lane) sh[w] = s;
        __syncthreads();
        if (w == 0) {
            int v = sh[lane];
            int ex = v;
            #pragma unroll
            for (int o = 1; o < 32; o <<= 1) {
                int u = __shfl_up_sync(0xFFFFFFFFu, ex, o);
                if (lane >= o) ex += u;
            }
            if (lane == 31) g_off[NN] = ex;
            sh[lane] = ex - v;
        }
        __syncthreads();
        int carry = sh[w];
        for (int k = 0; k < 64; k++) {
            int v = g_deg[base + k * 32 + lane];
            int inc = v;
            #pragma unroll
            for (int o = 1; o < 32; o <<= 1) {
                int u = __shfl_up_sync(0xFFFFFFFFu, inc, o);
                if (lane >= o) inc += u;
            }
            int ex = carry + inc - v;
            g_off[base + k * 32 + lane] = ex;
            g_cur[base + k * 32 + lane] = ex;
            carry += __shfl_sync(0xFFFFFFFFu, inc, 31);
        }
    } else {
        int a0 = g_gcnt[2 * t], a1 = g_gcnt[2 * t + 1];
        int s = a0 + a1;
        sh[t] = s;
        __syncthreads();
        for (int d = 1; d < 1024; d <<= 1) {
            int v = (t >= d) ? sh[t - d] : 0;
            __syncthreads();
            sh[t] += v;
            __syncthreads();
        }
        int off = sh[t] - s;
        g_gstart[2 * t] = off;
        g_gstart[2 * t + 1] = off + a0;
    }
}

// ---------------------- weight splitting (all in one launch) ----------------
__device__ __forceinline__ void splitw_seg(const float* W, __nv_bfloat16* oh,
                                           __nv_bfloat16* ol, int K, int Nn, int Kp) {
    GSTRIDE(idx, Nn * Kp) {
        int n = idx / Kp, k = idx % Kp;
        float v = (k < K) ? W[(size_t)k * Nn + n] : 0.f;
        __nv_bfloat16 hi, lo;
        split_bf16(v, hi, lo);
        oh[idx] = hi;
        ol[idx] = lo;
    }
}
__global__ void k_splitw_all(const float* __restrict__ gW1, const float* __restrict__ gW2,
                             const float* __restrict__ vW1, const float* __restrict__ vW2,
                             const float* __restrict__ Wp1) {
    int y = blockIdx.y;
    if (y < LL) {
        splitw_seg(gW1 + (size_t)y * HH * H2, g_gW1h + (size_t)y * H2 * KP1,
                   g_gW1l + (size_t)y * H2 * KP1, HH, H2, KP1);
    } else if (y < 2 * LL) {
        int l = y - LL;
        splitw_seg(gW2 + (size_t)l * H2 * HH, g_gW2h + (size_t)l * HH * KP2,
                   g_gW2l + (size_t)l * HH * KP2, H2, HH, KP2);
    } else if (y < 2 * LL + 4) {
        int l = y - 2 * LL;
        splitw_seg(vW1 + (size_t)l * HH * H2, g_vW1h + (size_t)l * H2 * KP1,
                   g_vW1l + (size_t)l * H2 * KP1, HH, H2, KP1);
    } else if (y < 2 * LL + 8) {
        int l = y - 2 * LL - 4;
        splitw_seg(vW2 + (size_t)l * H2 * HH, g_vW2h + (size_t)l * HH * KP2,
                   g_vW2l + (size_t)l * HH * KP2, H2, HH, KP2);
    } else {
        splitw_seg(Wp1, g_Wph, g_Wpl, DGC, H2, KPP);
    }
}

// ---------------------- mma.sync GEMM (two-region merged, 2-stage) ----------
#define RS_B 80
#define A_OFF 0
#define AL_OFF 10240
#define BH_OFF 20480
#define BL_OFF 30720
#define STAGE 40960
#define SMEMSZ (2 * STAGE)

#define MMA(c, a, b0v, b1v) \
    asm volatile("mma.sync.aligned.m16n8k16.row.col.f32.bf16.bf16.f32 " \
                 "{%0,%1,%2,%3},{%4,%5,%6,%7},{%8,%9},{%0,%1,%2,%3};" \
                 : "+f"((c)[0]), "+f"((c)[1]), "+f"((c)[2]), "+f"((c)[3]) \
                 : "r"((a)[0]), "r"((a)[1]), "r"((a)[2]), "r"((a)[3]), \
                   "r"(b0v), "r"(b1v))
#define CP16(dst, src) \
    asm volatile("cp.async.cg.shared.global [%0], [%1], 16;" :: "r"(dst), "l"(src))
#define CPCOMMIT asm volatile("cp.async.commit_group;" ::: "memory")
#define CPWAIT1 asm volatile("cp.async.wait_group 1;" ::: "memory")
#define CPWAIT0 asm volatile("cp.async.wait_group 0;" ::: "memory")

__device__ __forceinline__ void ldsm4(uint32_t& r0, uint32_t& r1, uint32_t& r2,
                                      uint32_t& r3, uint32_t a) {
    asm volatile("ldmatrix.sync.aligned.m8n8.x4.shared.b16 {%0,%1,%2,%3}, [%4];"
                 : "=r"(r0), "=r"(r1), "=r"(r2), "=r"(r3) : "r"(a));
}

template <int CFG>
__global__ void __launch_bounds__(256)
k_mma(const __nv_bfloat16* __restrict__ Ah1, const __nv_bfloat16* __restrict__ Al1,
      const __nv_bfloat16* __restrict__ Bh1, const __nv_bfloat16* __restrict__ Bl1,
      const float* __restrict__ bias1, float* __restrict__ F1,
      __nv_bfloat16* __restrict__ H1, __nv_bfloat16* __restrict__ L1,
      const __nv_bfloat16* __restrict__ Ah2, const __nv_bfloat16* __restrict__ Al2,
      const __nv_bfloat16* __restrict__ Bh2, const __nv_bfloat16* __restrict__ Bl2,
      const float* __restrict__ bias2, float* __restrict__ F2,
      __nv_bfloat16* __restrict__ H2o, __nv_bfloat16* __restrict__ L2o,
      int My1, int K, int N, int ldc) {
    extern __shared__ __align__(16) char sm[];
    const uint32_t sb = smem_u32(sm);
    const int tid = threadIdx.x, wid = tid >> 5, lane = tid & 31;
    const bool rg2 = (int)blockIdx.y >= My1;
    const int by = rg2 ? (int)blockIdx.y - My1 : (int)blockIdx.y;
    const __nv_bfloat16* Ah = rg2 ? Ah2 : Ah1;
    const __nv_bfloat16* Al = rg2 ? Al2 : Al1;
    const __nv_bfloat16* Bh = rg2 ? Bh2 : Bh1;
    const __nv_bfloat16* Bl = rg2 ? Bl2 : Bl1;
    const float* bias = rg2 ? bias2 : bias1;
    const int bm = by << 7, n0 = (int)blockIdx.x << 7;
    const int NC = K >> 5;
    const int nv = (N - n0) < 128 ? (N - n0) : 128;

    auto load_stage = [&](int c, int s) {
        char* bufc = sm + s * STAGE;
        uint32_t bufu = sb + s * STAGE;
        const int kh0 = c << 5;
        #pragma unroll
        for (int u = 0; u < 2; u++) {
            int idx = tid + (u << 8);
            int r = idx >> 2, kc = idx & 3;
            uint32_t doff = (uint32_t)r * RS_B + ((uint32_t)kc << 4);
            size_t go = (size_t)(bm + r) * K + kh0 + (kc << 3);
            CP16(bufu + A_OFF + doff, Ah + go);
            CP16(bufu + AL_OFF + doff, Al + go);
        }
        #pragma unroll
        for (int u = 0; u < 2; u++) {
            int idx = tid + (u << 8);
            int r = idx >> 2, kc = idx & 3;
            uint32_t doff = (uint32_t)r * RS_B + ((uint32_t)kc << 4);
            int gn = n0 + r;
            if (gn < N) {
                size_t go = (size_t)gn * K + kh0 + (kc << 3);
                CP16(bufu + BH_OFF + doff, Bh + go);
                CP16(bufu + BL_OFF + doff, Bl + go);
            } else {
                uint4 z = make_uint4(0, 0, 0, 0);
                *(uint4*)(bufc + BH_OFF + doff) = z;
                *(uint4*)(bufc + BL_OFF + doff) = z;
            }
        }
    };

    const int wm = (wid & 3) << 5, wn = (wid >> 2) << 6;
    const int wrem = nv - wn;
    const uint32_t aBase = (uint32_t)((wm + (lane & 15)) * RS_B + ((lane >> 4) << 4));
    const uint32_t bBase = (uint32_t)((wn + ((lane >> 4) << 3) + (lane & 7)) * RS_B +
                                      (((lane >> 3) & 1) << 4));

    float acc[2][8][4];
    #pragma unroll
    for (int a = 0; a < 2; a++)
        #pragma unroll
        for (int b = 0; b < 8; b++)
            #pragma unroll
            for (int q = 0; q < 4; q++) acc[a][b][q] = 0.f;

    load_stage(0, 0);
    CPCOMMIT;
    if (NC > 1) load_stage(1, 1);
    CPCOMMIT;

    for (int c = 0; c < NC; c++) {
        if (c == NC - 1) { CPWAIT0; } else { CPWAIT1; }
        __syncthreads();
        uint32_t st = sb + (c & 1) * STAGE;
        if (wrem > 0) {
            #pragma unroll
            for (int kb = 0; kb < 64; kb += 32) {
                uint32_t ah0[4], ah1[4], al0[4], al1[4];
                ldsm4(ah0[0], ah0[1], ah0[2], ah0[3], st + A_OFF + aBase + kb);
                ldsm4(ah1[0], ah1[1], ah1[2], ah1[3], st + A_OFF + aBase + 16 * RS_B + kb);
                ldsm4(al0[0], al0[1], al0[2], al0[3], st + AL_OFF + aBase + kb);
                ldsm4(al1[0], al1[1], al1[2], al1[3], st + AL_OFF + aBase + 16 * RS_B + kb);
                #pragma unroll
                for (int nt = 0; nt < 4; nt++) {
                    if (nt * 16 < wrem) {
                        uint32_t bh[4], bl[4];
                        ldsm4(bh[0], bh[1], bh[2], bh[3],
                              st + BH_OFF + bBase + nt * 16 * RS_B + kb);
                        ldsm4(bl[0], bl[1], bl[2], bl[3],
                              st + BL_OFF + bBase + nt * 16 * RS_B + kb);
                        MMA(acc[0][2 * nt],     ah0, bh[0], bh[1]);
                        MMA(acc[0][2 * nt + 1], ah0, bh[2], bh[3]);
                        MMA(acc[1][2 * nt],     ah1, bh[0], bh[1]);
                        MMA(acc[1][2 * nt + 1], ah1, bh[2], bh[3]);
                        MMA(acc[0][2 * nt],     ah0, bl[0], bl[1]);
                        MMA(acc[0][2 * nt + 1], ah0, bl[2], bl[3]);
                        MMA(acc[1][2 * nt],     ah1, bl[0], bl[1]);
                        MMA(acc[1][2 * nt + 1], ah1, bl[2], bl[3]);
                        MMA(acc[0][2 * nt],     al0, bh[0], bh[1]);
                        MMA(acc[0][2 * nt + 1], al0, bh[2], bh[3]);
                        MMA(acc[1][2 * nt],     al1, bh[0], bh[1]);
                        MMA(acc[1][2 * nt + 1], al1, bh[2], bh[3]);
                    }
                }
            }
        }
        __syncthreads();
        if (c + 2 < NC) {
            load_stage(c + 2, c & 1);
            CPCOMMIT;
        }
    }

    // epilogue
    const int r0 = bm + wm + (lane >> 2);
    const int cbl = n0 + wn + ((lane & 3) << 1);
    if (CFG == 0) {
        __nv_bfloat16* Ch = rg2 ? H2o : H1;
        __nv_bfloat16* Cl = rg2 ? L2o : L1;
        #pragma unroll
        for (int mt = 0; mt < 2; mt++) {
            #pragma unroll
            for (int nf = 0; nf < 8; nf++) {
                int col = cbl + (nf << 3);
                if (col >= N) continue;
                float2 bv = *(const float2*)(bias + col);
                int row = r0 + (mt << 4);
                float v0 = fmaxf(acc[mt][nf][0] + bv.x, 0.f);
                float v1 = fmaxf(acc[mt][nf][1] + bv.y, 0.f);
                float v2 = fmaxf(acc[mt][nf][2] + bv.x, 0.f);
                float v3 = fmaxf(acc[mt][nf][3] + bv.y, 0.f);
                __nv_bfloat16 h0, l0, h1, l1;
                split_bf16(v0, h0, l0);
                split_bf16(v1, h1, l1);
                size_t w0 = ((size_t)row * ldc + col) >> 1;
                ((uint32_t*)Ch)[w0] = pack2(h0, h1);
                ((uint32_t*)Cl)[w0] = pack2(l0, l1);
                split_bf16(v2, h0, l0);
                split_bf16(v3, h1, l1);
                size_t w1 = ((size_t)(row + 8) * ldc + col) >> 1;
                ((uint32_t*)Ch)[w1] = pack2(h0, h1);
                ((uint32_t*)Cl)[w1] = pack2(l0, l1);
            }
        }
    } else if (CFG == 1) {
        if (!rg2) {
            #pragma unroll
            for (int mt = 0; mt < 2; mt++) {
                #pragma unroll
                for (int nf = 0; nf < 8; nf++) {
                    int col = cbl + (nf << 3);
                    if (col >= N) continue;
                    float2 bv = *(const float2*)(bias + col);
                    int row = r0 + (mt << 4);
                    *(float2*)(F1 + (size_t)row * ldc + col) =
                        make_float2(acc[mt][nf][0] + bv.x, acc[mt][nf][1] + bv.y);
                    *(float2*)(F1 + (size_t)(row + 8) * ldc + col) =
                        make_float2(acc[mt][nf][2] + bv.x, acc[mt][nf][3] + bv.y);
                }
            }
            #pragma unroll
            for (int nf = 0; nf < 8; nf++) {
                int col = cbl + (nf << 3);
                bool ok = col < N;
                float2 bv = ok ? *(const float2*)(bias + col) : make_float2(0.f, 0.f);
                float s0 = 0.f, q0 = 0.f, s1 = 0.f, q1 = 0.f;
                #pragma unroll
                for (int mt = 0; mt < 2; mt++) {
                    float v0 = acc[mt][nf][0] + bv.x, v1 = acc[mt][nf][1] + bv.y;
                    float v2 = acc[mt][nf][2] + bv.x, v3 = acc[mt][nf][3] + bv.y;
                    s0 += v0 + v2; q0 += v0 * v0 + v2 * v2;
                    s1 += v1 + v3; q1 += v1 * v1 + v3 * v3;
                }
                #pragma unroll
                for (int o = 4; o < 32; o <<= 1) {
                    s0 += __shfl_xor_sync(0xFFFFFFFFu, s0, o);
                    q0 += __shfl_xor_sync(0xFFFFFFFFu, q0, o);
                    s1 += __shfl_xor_sync(0xFFFFFFFFu, s1, o);
                    q1 += __shfl_xor_sync(0xFFFFFFFFu, q1, o);
                }
                if (lane < 4 && ok) {
                    atomicAdd(&g_stats[col], s0);
                    atomicAdd(&g_stats[col + 1], s1);
                    atomicAdd(&g_stats[HH + col], q0);
                    atomicAdd(&g_stats[HH + col + 1], q1);
                }
            }
        } else {
            #pragma unroll
            for (int mt = 0; mt < 2; mt++) {
                #pragma unroll
                for (int nf = 0; nf < 8; nf++) {
                    int col = cbl + (nf << 3);
                    if (col >= N) continue;
                    float2 bv = *(const float2*)(bias + col);
                    int row = r0 + (mt << 4);
                    float v0 = fmaxf(acc[mt][nf][0] + bv.x, 0.f);
                    float v1 = fmaxf(acc[mt][nf][1] + bv.y, 0.f);
                    float v2 = fmaxf(acc[mt][nf][2] + bv.x, 0.f);
                    float v3 = fmaxf(acc[mt][nf][3] + bv.y, 0.f);
                    float2 o0 = *(const float2*)(F2 + (size_t)row * ldc + col);
                    float2 o1 = *(const float2*)(F2 + (size_t)(row + 8) * ldc + col);
                    *(float2*)(F2 + (size_t)row * ldc + col) =
                        make_float2(o0.x + v0, o0.y + v1);
                    *(float2*)(F2 + (size_t)(row + 8) * ldc + col) =
                        make_float2(o1.x + v2, o1.y + v3);
                }
            }
        }
    } else {
        float s[4] = {0.f, 0.f, 0.f, 0.f};
        #pragma unroll
        for (int mt = 0; mt < 2; mt++) {
            #pragma unroll
            for (int nf = 0; nf < 8; nf++) {
                int col = cbl + (nf << 3);
                if (col < N) {
                    float2 bv = *(const float2*)(bias + col);
                    float w0 = bias2[col], w1 = bias2[col + 1];
                    float v0 = fmaxf(acc[mt][nf][0] + bv.x, 0.f);
                    float v1 = fmaxf(acc[mt][nf][1] + bv.y, 0.f);
                    float v2 = fmaxf(acc[mt][nf][2] + bv.x, 0.f);
                    float v3 = fmaxf(acc[mt][nf][3] + bv.y, 0.f);
                    s[2 * mt] += v0 * w0 + v1 * w1;
                    s[2 * mt + 1] += v2 * w0 + v3 * w1;
                }
            }
        }
        #pragma unroll
        for (int q = 0; q < 4; q++) {
            s[q] += __shfl_xor_sync(0xFFFFFFFFu, s[q], 1);
            s[q] += __shfl_xor_sync(0xFFFFFFFFu, s[q], 2);
        }
        if ((lane & 3) == 0) {
            atomicAdd(&F2[r0], s[0]);
            atomicAdd(&F2[r0 + 8], s[1]);
            atomicAdd(&F2[r0 + 16], s[2]);
            atomicAdd(&F2[r0 + 24], s[3]);
        }
    }
}

// --------- BN apply (scalar) + hv production for the next layer -------------
__global__ void k_bnapply(const float* __restrict__ scale, const float* __restrict__ bias,
                          const int* __restrict__ batch, int vnl) {
    int j = threadIdx.x;
    if (j >= HH) return;
    const float invN = 1.f / (float)NN;
    float m = g_stats[j] * invN;
    float var = g_stats[HH + j] * invN - m * m;
    float co = rsqrtf(var + 1e-5f) * scale[j];
    float bi = bias[j];
    #pragma unroll
    for (int r = 0; r < 4; r++) {
        int node = blockIdx.x * 4 + r;
        size_t o = (size_t)node * HH + j;
        float z = (g_z2[o] - m) * co + bi;
        if (vnl) z = fmaxf(z, 0.f);
        float hn = g_h[o] + z;
        g_h[o] = hn;
        if (vnl) g_hv[o] = hn + g_vn[(size_t)batch[node] * HH + j];
    }
}

// ---------------------------------------------------------------------------
static inline int nblk(long long work, int t) { return (int)((work + t - 1) / t); }

extern "C" void kernel_launch(void* const* d_in, const int* in_sizes, int n_in,
                              void* d_out, int out_size) {
    const void* ord[21];
    int p = 0;
    const int* edge = nullptr;
    const int* batch = nullptr;
    for (int i = 0; i < n_in; i++) {
        if (in_sizes[i] == 2 * EE) edge = (const int*)d_in[i];
        else if (in_sizes[i] == NN) batch = (const int*)d_in[i];
        else if (p < 21) ord[p++] = d_in[i];
    }
    const float* x        = (const float*)ord[0];
    const float* morgan   = (const float*)ord[1];
    const float* maccs    = (const float*)ord[2];
    const float* W_emb    = (const float*)ord[3];
    const float* b_emb    = (const float*)ord[4];
    const float* gin_W1   = (const float*)ord[5];
    const float* gin_b1   = (const float*)ord[6];
    const float* gin_W2   = (const float*)ord[7];
    const float* gin_b2   = (const float*)ord[8];
    const float* bn_scale = (const float*)ord[9];
    const float* bn_bias  = (const float*)ord[10];
    const float* eps      = (const float*)ord[11];
    const float* vn0      = (const float*)ord[12];
    const float* vn_W1    = (const float*)ord[13];
    const float* vn_b1    = (const float*)ord[14];
    const float* vn_W2    = (const float*)ord[15];
    const float* vn_b2    = (const float*)ord[16];
    const float* Wp1      = (const float*)ord[17];
    const float* bp1      = (const float*)ord[18];
    const float* Wp2      = (const float*)ord[19];
    const float* bp2      = (const float*)ord[20];
    const int* src = edge;
    const int* dst = edge + EE;
    float* out = (float*)d_out;

    float *pz2, *pvn;
    __nv_bfloat16 *pzinh, *pzinl, *pt1h, *pt1l, *pvth, *pvtl, *pvhh, *pvhl, *phrh, *phrl;
    __nv_bfloat16 *pgW1h, *pgW1l, *pgW2h, *pgW2l, *pvW1h, *pvW1l, *pvW2h, *pvW2l, *pWph, *pWpl;
    cudaGetSymbolAddress((void**)&pz2, g_z2);
    cudaGetSymbolAddress((void**)&pvn, g_vn);
    cudaGetSymbolAddress((void**)&pzinh, g_zinh);
    cudaGetSymbolAddress((void**)&pzinl, g_zinl);
    cudaGetSymbolAddress((void**)&pt1h, g_t1h);
    cudaGetSymbolAddress((void**)&pt1l, g_t1l);
    cudaGetSymbolAddress((void**)&pvth, g_vth);
    cudaGetSymbolAddress((void**)&pvtl, g_vtl);
    cudaGetSymbolAddress((void**)&pvhh, g_vhh);
    cudaGetSymbolAddress((void**)&pvhl, g_vhl);
    cudaGetSymbolAddress((void**)&phrh, g_hreph);
    cudaGetSymbolAddress((void**)&phrl, g_hrepl);
    cudaGetSymbolAddress((void**)&pgW1h, g_gW1h);
    cudaGetSymbolAddress((void**)&pgW1l, g_gW1l);
    cudaGetSymbolAddress((void**)&pgW2h, g_gW2h);
    cudaGetSymbolAddress((void**)&pgW2l, g_gW2l);
    cudaGetSymbolAddress((void**)&pvW1h, g_vW1h);
    cudaGetSymbolAddress((void**)&pvW1l, g_vW1l);
    cudaGetSymbolAddress((void**)&pvW2h, g_vW2h);
    cudaGetSymbolAddress((void**)&pvW2l, g_vW2l);
    cudaGetSymbolAddress((void**)&pWph, g_Wph);
    cudaGetSymbolAddress((void**)&pWpl, g_Wpl);

    cudaFuncSetAttribute(k_mma<0>, cudaFuncAttributeMaxDynamicSharedMemorySize, SMEMSZ);
    cudaFuncSetAttribute(k_mma<1>, cudaFuncAttributeMaxDynamicSharedMemorySize, SMEMSZ);
    cudaFuncSetAttribute(k_mma<2>, cudaFuncAttributeMaxDynamicSharedMemorySize, SMEMSZ);

    const int T = 256;

    // setup
    k_embed<<<NN / 4, 320>>>(x, W_emb, b_emb, vn0);
    k_setup<<<nblk(NN + GG + GG * HH, T), T>>>(vn0, bp2, out);
    k_splitw_all<<<dim3(512, 19), T>>>(gin_W1, gin_W2, vn_W1, vn_W2, Wp1);
    k_hist<<<nblk(EE, T), T>>>(dst, batch);
    k_scan_both<<<2, 1024>>>();
    k_scatter<<<nblk(EE, T), T>>>(src, dst);

    for (int l = 0; l < LL; l++) {
        bool vnl = l < LL - 1;
        int vtb = vnl ? GG / 8 : 0;
        k_gather<<<vtb + NN / 8, 256>>>(eps, l, vtb);

        int gy = 512 + (vnl ? 16 : 0);
        k_mma<0><<<dim3(5, gy), 256, SMEMSZ>>>(
            pzinh, pzinl,
            pgW1h + (size_t)l * H2 * KP1, pgW1l + (size_t)l * H2 * KP1,
            gin_b1 + (size_t)l * H2, nullptr, pt1h, pt1l,
            pvth, pvtl,
            vnl ? pvW1h + (size_t)l * H2 * KP1 : nullptr,
            vnl ? pvW1l + (size_t)l * H2 * KP1 : nullptr,
            vnl ? vn_b1 + (size_t)l * H2 : nullptr, nullptr, pvhh, pvhl,
            512, KP1, H2, KP2);
        k_mma<1><<<dim3(3, gy), 256, SMEMSZ>>>(
            pt1h, pt1l,
            pgW2h + (size_t)l * HH * KP2, pgW2l + (size_t)l * HH * KP2,
            gin_b2 + (size_t)l * HH, pz2, nullptr, nullptr,
            pvhh, pvhl,
            vnl ? pvW2h + (size_t)l * HH * KP2 : nullptr,
            vnl ? pvW2l + (size_t)l * HH * KP2 : nullptr,
            vnl ? vn_b2 + (size_t)l * HH : nullptr, pvn, nullptr, nullptr,
            512, KP2, HH, HH);

        k_bnapply<<<NN / 4, 320>>>(bn_scale + (size_t)l * HH,
                                   bn_bias + (size_t)l * HH, batch, vnl ? 1 : 0);
    }

    k_poolassemble<<<GG / 8, 256>>>(morgan, maccs);
    k_mma<2><<<dim3(5, 16), 256, SMEMSZ>>>(
        phrh, phrl, pWph, pWpl, bp1, nullptr, nullptr, nullptr,
        nullptr, nullptr, nullptr, nullptr, Wp2, out, nullptr, nullptr,
        16, KPP, H2, H2);
}